// round 1
// baseline (speedup 1.0000x reference)
#include <cuda_runtime.h>
#include <cstdint>

#define B_   2048
#define N_   10
#define M_   11          // N+1 (context + nodes)
#define H_   256
#define LD_  8
#define L_   4
#define FF_  1024
#define NT_  5

// ---------------- scratch (device globals; no runtime allocation) -------------
__device__ float g_ctx [B_*H_];
__device__ float g_mem [B_*M_*H_];
__device__ float g_h   [B_*N_*H_];
__device__ float g_q   [B_*N_*H_];
__device__ float g_k   [B_*M_*H_];
__device__ float g_v   [B_*M_*H_];
__device__ float g_o   [B_*N_*H_];
__device__ float g_y   [B_*N_*H_];
__device__ float g_ffn [B_*N_*FF_];
__device__ float g_U   [NT_*N_*H_];   // (type,pos) -> ne @ W1a
__device__ float g_Vt  [NT_*N_*H_];   // (type,pos) -> ne @ W1b
__device__ float g_wlat[B_*H_];       // latent @ W1c + edge_b1

// ---------------- helpers ------------------------------------------------------
__device__ __forceinline__ float2 block_meanvar_256(float x, float* sbuf)
{
    float s = x, s2 = x * x;
    #pragma unroll
    for (int o = 16; o; o >>= 1) {
        s  += __shfl_xor_sync(0xffffffffu, s,  o);
        s2 += __shfl_xor_sync(0xffffffffu, s2, o);
    }
    int w = threadIdx.x >> 5;
    if ((threadIdx.x & 31) == 0) { sbuf[w] = s; sbuf[8 + w] = s2; }
    __syncthreads();
    float ts = 0.f, ts2 = 0.f;
    #pragma unroll
    for (int i = 0; i < 8; i++) { ts += sbuf[i]; ts2 += sbuf[8 + i]; }
    __syncthreads();
    float mean = ts * (1.f / 256.f);
    float var  = ts2 * (1.f / 256.f) - mean * mean;
    return make_float2(mean, rsqrtf(var + 1e-5f));
}

// ---------------- context encoder + node-count head + h/mem init ---------------
__global__ void k_context(
    const float* __restrict__ lat, const int* __restrict__ types,
    const float* __restrict__ w1, const float* __restrict__ b1,
    const float* __restrict__ g1, const float* __restrict__ be1,
    const float* __restrict__ w2, const float* __restrict__ b2,
    const float* __restrict__ g2, const float* __restrict__ be2,
    const float* __restrict__ ncw1, const float* __restrict__ ncb1,
    const float* __restrict__ ncw2, const float* __restrict__ ncb2,
    const float* __restrict__ temb, const float* __restrict__ pemb,
    float* __restrict__ out_nc)
{
    int b = blockIdx.x, t = threadIdx.x;
    __shared__ float sl[8];
    __shared__ float sh0[256];
    __shared__ float sred[16];
    __shared__ float snc[64];
    __shared__ int   sty[10];
    if (t < 8)  sl[t]  = lat[b * LD_ + t];
    if (t < 10) sty[t] = types[b * N_ + t];
    __syncthreads();

    float x = b1[t];
    #pragma unroll
    for (int k = 0; k < 8; k++) x += sl[k] * w1[k * H_ + t];
    float2 mv = block_meanvar_256(x, sred);
    float h0 = fmaxf((x - mv.x) * mv.y * g1[t] + be1[t], 0.f);
    sh0[t] = h0;
    __syncthreads();

    float y = b2[t];
    for (int k = 0; k < 256; k++) y += sh0[k] * w2[k * H_ + t];
    mv = block_meanvar_256(y, sred);
    float ctx = (y - mv.x) * mv.y * g2[t] + be2[t];

    g_ctx[b * H_ + t] = ctx;
    g_mem[(size_t)b * (M_ * H_) + t] = ctx;   // mem row 0 = context
    #pragma unroll
    for (int i = 0; i < N_; i++) {
        float pe = pemb[i * H_ + t];
        g_h  [((size_t)b * N_ + i) * H_ + t]       = ctx + pe;
        g_mem[((size_t)b * M_ + 1 + i) * H_ + t]   = temb[sty[i] * H_ + t] + pe;
    }

    // node-count head
    if (t < 64) snc[t] = fmaxf(sl[0] * ncw1[t] + sl[1] * ncw1[64 + t] + ncb1[t], 0.f);
    __syncthreads();
    if (t < 3) {
        float o = ncb2[t];
        #pragma unroll
        for (int k = 0; k < 64; k++) o += snc[k] * ncw2[k * 3 + t];
        out_nc[b * 3 + t] = o;
    }
}

// ---------------- tiled SGEMM, 128x128x16, fp32 with packed FFMA2 --------------
// C[M,N] = A[M,K] @ W[K,N] + bias[N], optional relu. M%128==0, N%128==0, K%16==0.
__global__ __launch_bounds__(256, 2)
void k_gemm(const float* __restrict__ A, const float* __restrict__ W,
            const float* __restrict__ bias, float* __restrict__ C,
            int M, int N, int K, int relu)
{
    __shared__ float sA[16][128];
    __shared__ float sW[16][128];
    const int tid = threadIdx.x;
    const int bn = blockIdx.x * 128;
    const int bm = blockIdx.y * 128;
    const int tx = tid & 15, ty = tid >> 4;

    unsigned long long acc[8][4];
    #pragma unroll
    for (int i = 0; i < 8; i++)
        #pragma unroll
        for (int j = 0; j < 4; j++) acc[i][j] = 0ull;

    for (int k0 = 0; k0 < K; k0 += 16) {
        #pragma unroll
        for (int r = 0; r < 2; r++) {
            int id = tid * 2 + r;                 // 0..511
            int row = id >> 2, kq = id & 3;
            float4 v = *reinterpret_cast<const float4*>(
                A + (size_t)(bm + row) * K + k0 + kq * 4);
            sA[kq * 4 + 0][row] = v.x;
            sA[kq * 4 + 1][row] = v.y;
            sA[kq * 4 + 2][row] = v.z;
            sA[kq * 4 + 3][row] = v.w;
        }
        #pragma unroll
        for (int r = 0; r < 2; r++) {
            int id = tid * 2 + r;
            int kk = id >> 5, nq = id & 31;
            *reinterpret_cast<float4*>(&sW[kk][nq * 4]) =
                *reinterpret_cast<const float4*>(W + (size_t)(k0 + kk) * N + bn + nq * 4);
        }
        __syncthreads();
        #pragma unroll
        for (int kk = 0; kk < 16; kk++) {
            unsigned long long aa[8], ww[4];
            #pragma unroll
            for (int i = 0; i < 8; i++) {
                unsigned ai = __float_as_uint(sA[kk][ty * 8 + i]);
                asm("mov.b64 %0, {%1, %1};" : "=l"(aa[i]) : "r"(ai));
            }
            #pragma unroll
            for (int j = 0; j < 4; j++)
                ww[j] = *reinterpret_cast<const unsigned long long*>(&sW[kk][tx * 8 + 2 * j]);
            #pragma unroll
            for (int i = 0; i < 8; i++)
                #pragma unroll
                for (int j = 0; j < 4; j++)
                    asm("fma.rn.f32x2 %0, %1, %2, %0;"
                        : "+l"(acc[i][j]) : "l"(aa[i]), "l"(ww[j]));
        }
        __syncthreads();
    }

    float bv[8];
    #pragma unroll
    for (int j = 0; j < 8; j++) bv[j] = bias[bn + tx * 8 + j];
    #pragma unroll
    for (int i = 0; i < 8; i++) {
        float out[8];
        #pragma unroll
        for (int j = 0; j < 4; j++) {
            out[2 * j]     = __uint_as_float((unsigned)(acc[i][j] & 0xffffffffull)) + bv[2 * j];
            out[2 * j + 1] = __uint_as_float((unsigned)(acc[i][j] >> 32))           + bv[2 * j + 1];
        }
        if (relu) {
            #pragma unroll
            for (int j = 0; j < 8; j++) out[j] = fmaxf(out[j], 0.f);
        }
        float4* dst = reinterpret_cast<float4*>(C + (size_t)(bm + ty * 8 + i) * N + bn + tx * 8);
        dst[0] = make_float4(out[0], out[1], out[2], out[3]);
        dst[1] = make_float4(out[4], out[5], out[6], out[7]);
    }
}

// ---------------- attention: one block per batch, warp per head ----------------
__global__ void k_attn()
{
    int b = blockIdx.x;
    int h = threadIdx.x >> 5, d = threadIdx.x & 31;
    const float* Qb = g_q + (size_t)b * N_ * H_;
    const float* Kb = g_k + (size_t)b * M_ * H_;
    const float* Vb = g_v + (size_t)b * M_ * H_;
    float*       Ob = g_o + (size_t)b * N_ * H_;
    const float scale = 0.17677669529663687f;   // 1/sqrt(32)

    #pragma unroll
    for (int i = 0; i < N_; i++) {
        float q = Qb[i * H_ + h * 32 + d];
        float sown = -1e30f;
        for (int m = 0; m <= i; m++) {
            float p = q * Kb[m * H_ + h * 32 + d];
            #pragma unroll
            for (int o = 16; o; o >>= 1) p += __shfl_xor_sync(0xffffffffu, p, o);
            if (d == m) sown = p * scale;
        }
        float mx = sown;
        #pragma unroll
        for (int o = 16; o; o >>= 1) mx = fmaxf(mx, __shfl_xor_sync(0xffffffffu, mx, o));
        float e = (d <= i) ? __expf(sown - mx) : 0.f;
        float den = e;
        #pragma unroll
        for (int o = 16; o; o >>= 1) den += __shfl_xor_sync(0xffffffffu, den, o);
        float oacc = 0.f;
        for (int m = 0; m <= i; m++) {
            float a = __shfl_sync(0xffffffffu, e, m);
            oacc += a * Vb[m * H_ + h * 32 + d];
        }
        Ob[i * H_ + h * 32 + d] = oacc / den;
    }
}

// ---------------- residual + LayerNorm (in place on g_h) -----------------------
__global__ void k_resln(const float* __restrict__ y,
                        const float* __restrict__ g, const float* __restrict__ b)
{
    int r = blockIdx.x, t = threadIdx.x;
    __shared__ float sred[16];
    size_t idx = (size_t)r * H_ + t;
    float x = g_h[idx] + y[idx];
    float2 mv = block_meanvar_256(x, sred);
    g_h[idx] = (x - mv.x) * mv.y * g[t] + b[t];
}

// ---------------- node-logits head: warp per row --------------------------------
__global__ void k_head(const float* __restrict__ W, const float* __restrict__ bb,
                       float* __restrict__ out)
{
    int gid = blockIdx.x * blockDim.x + threadIdx.x;
    int row = gid >> 5, lane = gid & 31;
    if (row >= B_ * N_) return;
    const float* hr = g_h + (size_t)row * H_;
    float a0 = 0, a1 = 0, a2 = 0, a3 = 0, a4 = 0;
    #pragma unroll
    for (int qq = 0; qq < 8; qq++) {
        int k = lane + 32 * qq;
        float hv = hr[k];
        const float* w = W + k * 5;
        a0 += hv * w[0]; a1 += hv * w[1]; a2 += hv * w[2];
        a3 += hv * w[3]; a4 += hv * w[4];
    }
    #pragma unroll
    for (int o = 16; o; o >>= 1) {
        a0 += __shfl_xor_sync(0xffffffffu, a0, o);
        a1 += __shfl_xor_sync(0xffffffffu, a1, o);
        a2 += __shfl_xor_sync(0xffffffffu, a2, o);
        a3 += __shfl_xor_sync(0xffffffffu, a3, o);
        a4 += __shfl_xor_sync(0xffffffffu, a4, o);
    }
    if (lane < 5) {
        float v = (lane == 0) ? a0 : (lane == 1) ? a1 : (lane == 2) ? a2
                 : (lane == 3) ? a3 : a4;
        out[(size_t)row * 5 + lane] = v + bb[lane];
    }
}

// ---------------- edge decoder precompute --------------------------------------
// U[(t,p)] = (type_emb[t]+pos_emb[p]) @ W1[0:256],  V likewise with W1[256:512]
__global__ void k_edge_uv(const float* __restrict__ temb, const float* __restrict__ pemb,
                          const float* __restrict__ w1)
{
    int tt = blockIdx.x / N_, p = blockIdx.x % N_;
    int j = threadIdx.x;
    __shared__ float ne[256];
    ne[j] = temb[tt * H_ + j] + pemb[p * H_ + j];
    __syncthreads();
    float au = 0.f, av = 0.f;
    for (int k = 0; k < 256; k++) {
        float n = ne[k];
        au += n * w1[k * H_ + j];
        av += n * w1[(256 + k) * H_ + j];
    }
    g_U [blockIdx.x * H_ + j] = au;
    g_Vt[blockIdx.x * H_ + j] = av;
}

__global__ void k_wlat(const float* __restrict__ lat, const float* __restrict__ w1,
                       const float* __restrict__ b1)
{
    int b = blockIdx.x, t = threadIdx.x;
    __shared__ float sl[8];
    if (t < 8) sl[t] = lat[b * LD_ + t];
    __syncthreads();
    float a = b1[t];
    #pragma unroll
    for (int k = 0; k < 8; k++) a += sl[k] * w1[(2 * H_ + k) * H_ + t];
    g_wlat[b * H_ + t] = a;
}

// ---------------- edge decoder main: block per batch, 45 lower-tri pairs -------
__global__ void k_edge(const int* __restrict__ types,
                       const float* __restrict__ W2, const float* __restrict__ b2,
                       float* __restrict__ out)
{
    int b = blockIdx.x, t = threadIdx.x;
    __shared__ float s_w[256];
    __shared__ float s_hid[256];
    __shared__ float s_W2t[8 * 256];
    __shared__ float s_b2[8];
    __shared__ int   s_ty[10];

    s_w[t] = g_wlat[b * H_ + t];
    #pragma unroll
    for (int c = 0; c < 8; c++) s_W2t[c * 256 + t] = W2[t * 8 + c];
    if (t < 10) s_ty[t] = types[b * N_ + t];
    if (t < 8)  s_b2[t] = b2[t];

    float* eb = out + (size_t)b * (N_ * N_ * 8);
    if (t < 80) { int i = t / 8, c = t % 8; eb[(i * N_ + i) * 8 + c] = 0.f; }
    __syncthreads();

    int lane = t & 31, w = t >> 5;
    for (int i = 1; i < N_; i++) {
        for (int j = 0; j < i; j++) {
            float hv = s_w[t] + g_U[(s_ty[i] * N_ + i) * H_ + t]
                              + g_Vt[(s_ty[j] * N_ + j) * H_ + t];
            s_hid[t] = fmaxf(hv, 0.f);
            __syncthreads();
            float acc = 0.f;
            #pragma unroll
            for (int qq = 0; qq < 8; qq++)
                acc += s_hid[lane + 32 * qq] * s_W2t[w * 256 + lane + 32 * qq];
            #pragma unroll
            for (int o = 16; o; o >>= 1) acc += __shfl_xor_sync(0xffffffffu, acc, o);
            if (lane == 0) {
                float v = acc + s_b2[w];
                eb[(i * N_ + j) * 8 + w] = v;
                eb[(j * N_ + i) * 8 + w] = v;
            }
            __syncthreads();
        }
    }
}

// ---------------- launcher -------------------------------------------------------
extern "C" void kernel_launch(void* const* d_in, const int* in_sizes, int n_in,
                              void* d_out, int out_size)
{
    (void)in_sizes; (void)n_in; (void)out_size;
    const float* latent  = (const float*)d_in[0];
    const int*   types   = (const int*)  d_in[1];
    const float* ce_w1   = (const float*)d_in[2];
    const float* ce_b1   = (const float*)d_in[3];
    const float* ce_g1   = (const float*)d_in[4];
    const float* ce_be1  = (const float*)d_in[5];
    const float* ce_w2   = (const float*)d_in[6];
    const float* ce_b2   = (const float*)d_in[7];
    const float* ce_g2   = (const float*)d_in[8];
    const float* ce_be2  = (const float*)d_in[9];
    const float* nc_w1   = (const float*)d_in[10];
    const float* nc_b1   = (const float*)d_in[11];
    const float* nc_w2   = (const float*)d_in[12];
    const float* nc_b2   = (const float*)d_in[13];
    const float* type_emb= (const float*)d_in[14];
    const float* pos_emb = (const float*)d_in[15];
    const float* qkvo_w  = (const float*)d_in[16];
    const float* qkvo_b  = (const float*)d_in[17];
    const float* ln_g    = (const float*)d_in[18];
    const float* ln_b    = (const float*)d_in[19];
    const float* ffn_w1  = (const float*)d_in[20];
    const float* ffn_b1  = (const float*)d_in[21];
    const float* ffn_w2  = (const float*)d_in[22];
    const float* ffn_b2  = (const float*)d_in[23];
    const float* out_w   = (const float*)d_in[24];
    const float* out_b   = (const float*)d_in[25];
    const float* edge_w1 = (const float*)d_in[26];
    const float* edge_b1 = (const float*)d_in[27];
    const float* edge_w2 = (const float*)d_in[28];
    const float* edge_b2 = (const float*)d_in[29];

    float* out      = (float*)d_out;
    float* out_node = out;                                 // [B,N,5]
    float* out_nc   = out + (size_t)B_ * N_ * 5;           // [B,3]
    float* out_edge = out + (size_t)B_ * N_ * 5 + B_ * 3;  // [B,N,N,8]

    float *p_h, *p_mem, *p_q, *p_k, *p_v, *p_o, *p_y, *p_ffn;
    cudaGetSymbolAddress((void**)&p_h,   g_h);
    cudaGetSymbolAddress((void**)&p_mem, g_mem);
    cudaGetSymbolAddress((void**)&p_q,   g_q);
    cudaGetSymbolAddress((void**)&p_k,   g_k);
    cudaGetSymbolAddress((void**)&p_v,   g_v);
    cudaGetSymbolAddress((void**)&p_o,   g_o);
    cudaGetSymbolAddress((void**)&p_y,   g_y);
    cudaGetSymbolAddress((void**)&p_ffn, g_ffn);

    k_context<<<B_, 256>>>(latent, types, ce_w1, ce_b1, ce_g1, ce_be1,
                           ce_w2, ce_b2, ce_g2, ce_be2,
                           nc_w1, nc_b1, nc_w2, nc_b2,
                           type_emb, pos_emb, out_nc);
    k_edge_uv<<<NT_ * N_, 256>>>(type_emb, pos_emb, edge_w1);
    k_wlat<<<B_, 256>>>(latent, edge_w1, edge_b1);

    const int MQ = B_ * N_;   // 20480
    const int MK = B_ * M_;   // 22528

    for (int l = 0; l < L_; l++) {
        const float* Wq = qkvo_w + (size_t)(l * 4 + 0) * H_ * H_;
        const float* Wk = qkvo_w + (size_t)(l * 4 + 1) * H_ * H_;
        const float* Wv = qkvo_w + (size_t)(l * 4 + 2) * H_ * H_;
        const float* Wo = qkvo_w + (size_t)(l * 4 + 3) * H_ * H_;
        const float* bq = qkvo_b + (size_t)(l * 4 + 0) * H_;
        const float* bk = qkvo_b + (size_t)(l * 4 + 1) * H_;
        const float* bv = qkvo_b + (size_t)(l * 4 + 2) * H_;
        const float* bo = qkvo_b + (size_t)(l * 4 + 3) * H_;

        k_gemm<<<dim3(H_ / 128, MQ / 128), 256>>>(p_h,   Wq, bq, p_q, MQ, H_, H_, 0);
        k_gemm<<<dim3(H_ / 128, MK / 128), 256>>>(p_mem, Wk, bk, p_k, MK, H_, H_, 0);
        k_gemm<<<dim3(H_ / 128, MK / 128), 256>>>(p_mem, Wv, bv, p_v, MK, H_, H_, 0);
        k_attn<<<B_, 256>>>();
        k_gemm<<<dim3(H_ / 128, MQ / 128), 256>>>(p_o, Wo, bo, p_y, MQ, H_, H_, 0);
        k_resln<<<MQ, 256>>>(p_y, ln_g + (size_t)(l * 2 + 0) * H_, ln_b + (size_t)(l * 2 + 0) * H_);
        k_gemm<<<dim3(FF_ / 128, MQ / 128), 256>>>(p_h, ffn_w1 + (size_t)l * H_ * FF_,
                                                   ffn_b1 + (size_t)l * FF_, p_ffn, MQ, FF_, H_, 1);
        k_gemm<<<dim3(H_ / 128, MQ / 128), 256>>>(p_ffn, ffn_w2 + (size_t)l * FF_ * H_,
                                                  ffn_b2 + (size_t)l * H_, p_y, MQ, H_, FF_, 0);
        k_resln<<<MQ, 256>>>(p_y, ln_g + (size_t)(l * 2 + 1) * H_, ln_b + (size_t)(l * 2 + 1) * H_);
    }

    k_head<<<(B_ * N_ * 32) / 256, 256>>>(out_w, out_b, out_node);
    k_edge<<<B_, 256>>>(types, edge_w2, edge_b2, out_edge);
}

// round 3
// speedup vs baseline: 1.9908x; 1.9908x over previous
#include <cuda_runtime.h>
#include <cuda_bf16.h>
#include <cstdint>

#define B_   2048
#define N_   10
#define M_   11
#define H_   256
#define LD_  8
#define L_   4
#define FF_  1024
#define NT_  5

// ---------------- scratch -------------------------------------------------------
__device__ float g_ctx [B_*H_];
__device__ float g_mem [B_*M_*H_];
__device__ float g_h   [B_*N_*H_];
__device__ float g_q   [B_*N_*H_];
__device__ float g_k   [B_*M_*H_];
__device__ float g_v   [B_*M_*H_];
__device__ float g_o   [B_*N_*H_];
__device__ float g_y   [B_*N_*H_];
__device__ float g_ffn [B_*N_*FF_];
__device__ float g_U   [NT_*N_*H_];
__device__ float g_Vt  [NT_*N_*H_];
__device__ float g_wlat[B_*H_];
// transposed + bf16-split weights: per layer 786432 elems
// layout per layer: q@0, k@65536, v@131072, o@196608, f1@262144, f2@524288
__device__ __nv_bfloat16 g_wbh[(size_t)L_*786432];
__device__ __nv_bfloat16 g_wbl[(size_t)L_*786432];

// ---------------- helpers --------------------------------------------------------
__device__ __forceinline__ uint32_t smem_u32(const void* p){
    uint32_t a; asm("{ .reg .u64 t; cvta.to.shared.u64 t, %1; cvt.u32.u64 %0, t; }"
                    : "=r"(a) : "l"(p)); return a;
}
__device__ __forceinline__ uint32_t pack_bf2(float x, float y){
    __nv_bfloat162 t = __floats2bfloat162_rn(x, y);
    return *reinterpret_cast<uint32_t*>(&t);
}
__device__ __forceinline__ void ldm_x4(uint32_t* r, uint32_t addr){
    asm volatile("ldmatrix.sync.aligned.m8n8.x4.shared.b16 {%0,%1,%2,%3}, [%4];"
        : "=r"(r[0]),"=r"(r[1]),"=r"(r[2]),"=r"(r[3]) : "r"(addr));
}
__device__ __forceinline__ void mma_bf16(float* d, const uint32_t* a, const uint32_t* b){
    asm volatile("mma.sync.aligned.m16n8k16.row.col.f32.bf16.bf16.f32 "
        "{%0,%1,%2,%3}, {%4,%5,%6,%7}, {%8,%9}, {%0,%1,%2,%3};"
        : "+f"(d[0]),"+f"(d[1]),"+f"(d[2]),"+f"(d[3])
        : "r"(a[0]),"r"(a[1]),"r"(a[2]),"r"(a[3]), "r"(b[0]),"r"(b[1]));
}

// ---------------- weight prep: transpose + bf16 split -----------------------------
__global__ void k_prep_qkvo(const float* __restrict__ w){   // [L,4,K=H,N=H]
    int idx = blockIdx.x * 256 + threadIdx.x;
    int mat = idx >> 16, rem = idx & 65535;
    int k = rem >> 8, n = rem & 255;
    float v = w[idx];
    __nv_bfloat16 h = __float2bfloat16(v);
    float lo = v - __bfloat162float(h);
    int l = mat >> 2, m = mat & 3;
    size_t o = (size_t)l * 786432 + (size_t)m * 65536 + (size_t)n * 256 + k;
    g_wbh[o] = h; g_wbl[o] = __float2bfloat16(lo);
}
__global__ void k_prep_ffn1(const float* __restrict__ w){   // [L,256,1024]
    int idx = blockIdx.x * 256 + threadIdx.x;
    int l = idx >> 18, rem = idx & 262143;
    int k = rem >> 10, n = rem & 1023;
    float v = w[idx];
    __nv_bfloat16 h = __float2bfloat16(v);
    float lo = v - __bfloat162float(h);
    size_t o = (size_t)l * 786432 + 262144 + (size_t)n * 256 + k;
    g_wbh[o] = h; g_wbl[o] = __float2bfloat16(lo);
}
__global__ void k_prep_ffn2(const float* __restrict__ w){   // [L,1024,256]
    int idx = blockIdx.x * 256 + threadIdx.x;
    int l = idx >> 18, rem = idx & 262143;
    int k = rem >> 8, n = rem & 255;
    float v = w[idx];
    __nv_bfloat16 h = __float2bfloat16(v);
    float lo = v - __bfloat162float(h);
    size_t o = (size_t)l * 786432 + 524288 + (size_t)n * 1024 + k;
    g_wbh[o] = h; g_wbl[o] = __float2bfloat16(lo);
}

// ---------------- mma.sync bf16 split GEMM ----------------------------------------
// C[M,N] = A[M,K] @ W + bias, W pre-transposed/split as Bt[N,K] hi/lo (bf16).
// 128x128 tiles, K-chunks of 32. 256 threads: 8 warps, warp tile 32(M)x64(N).
#define ASTRIDE 40   // bf16 per smem row: 32 data + 8 pad (stride 5 x 16B units)

__global__ __launch_bounds__(256, 2)
void k_gemm_mma(const float* __restrict__ A,
                const __nv_bfloat16* __restrict__ Bth,
                const __nv_bfloat16* __restrict__ Btl,
                const float* __restrict__ bias, float* __restrict__ C,
                int M, int N, int K, int relu)
{
    __shared__ __nv_bfloat16 sAh[128*ASTRIDE], sAl[128*ASTRIDE];
    __shared__ __nv_bfloat16 sBh[128*ASTRIDE], sBl[128*ASTRIDE];

    const int tid = threadIdx.x;
    const int wid = tid >> 5, lane = tid & 31;
    const int warp_m = wid & 3, warp_n = wid >> 2;
    const int bm = blockIdx.y * 128, bn = blockIdx.x * 128;

    const uint32_t sAh_b = smem_u32(sAh), sAl_b = smem_u32(sAl);
    const uint32_t sBh_b = smem_u32(sBh), sBl_b = smem_u32(sBl);

    float acc[2][8][4];
    #pragma unroll
    for (int i = 0; i < 2; i++)
        #pragma unroll
        for (int j = 0; j < 8; j++)
            #pragma unroll
            for (int q = 0; q < 4; q++) acc[i][j][q] = 0.f;

    // per-lane ldmatrix address pieces
    const int sub  = lane >> 3;
    const int a_r  = (lane & 7) + ((sub & 1) << 3);   // row within 16, +khalf by sub>>1
    const int a_kc = (sub >> 1) << 3;
    const int b_n  = (lane & 7) + ((sub >> 1) << 3);
    const int b_kc = (sub & 1) << 3;

    for (int k0 = 0; k0 < K; k0 += 32) {
        #pragma unroll
        for (int r = 0; r < 2; r++) {
            int id  = tid + r * 256;            // 0..511
            int row = id >> 2, half = id & 3;
            int kk  = half << 3;
            const float* ap = A + (size_t)(bm + row) * K + k0 + kk;
            float4 v0 = *reinterpret_cast<const float4*>(ap);
            float4 v1 = *reinterpret_cast<const float4*>(ap + 4);
            float xs[8] = {v0.x, v0.y, v0.z, v0.w, v1.x, v1.y, v1.z, v1.w};
            uint32_t hw[4], lw[4];
            #pragma unroll
            for (int j = 0; j < 4; j++) {
                float a0 = xs[2*j], a1 = xs[2*j+1];
                float h0 = __bfloat162float(__float2bfloat16(a0));
                float h1 = __bfloat162float(__float2bfloat16(a1));
                hw[j] = pack_bf2(h0, h1);
                lw[j] = pack_bf2(a0 - h0, a1 - h1);
            }
            int so = row * ASTRIDE + kk;
            *reinterpret_cast<uint4*>(sAh + so) = make_uint4(hw[0], hw[1], hw[2], hw[3]);
            *reinterpret_cast<uint4*>(sAl + so) = make_uint4(lw[0], lw[1], lw[2], lw[3]);
            const __nv_bfloat16* bph = Bth + (size_t)(bn + row) * K + k0 + kk;
            const __nv_bfloat16* bpl = Btl + (size_t)(bn + row) * K + k0 + kk;
            *reinterpret_cast<uint4*>(sBh + so) = *reinterpret_cast<const uint4*>(bph);
            *reinterpret_cast<uint4*>(sBl + so) = *reinterpret_cast<const uint4*>(bpl);
        }
        __syncthreads();

        #pragma unroll
        for (int ks = 0; ks < 2; ks++) {
            uint32_t ah[2][4], al[2][4];
            #pragma unroll
            for (int mt = 0; mt < 2; mt++) {
                int rr = warp_m * 32 + mt * 16 + a_r;
                int kc = ks * 16 + a_kc;
                uint32_t off = (uint32_t)(rr * ASTRIDE + kc) * 2;
                ldm_x4(ah[mt], sAh_b + off);
                ldm_x4(al[mt], sAl_b + off);
            }
            #pragma unroll
            for (int np = 0; np < 4; np++) {
                int nr = warp_n * 64 + np * 16 + b_n;
                int kc = ks * 16 + b_kc;
                uint32_t off = (uint32_t)(nr * ASTRIDE + kc) * 2;
                uint32_t bh[4], bl[4];
                ldm_x4(bh, sBh_b + off);
                ldm_x4(bl, sBl_b + off);
                #pragma unroll
                for (int mt = 0; mt < 2; mt++) {
                    #pragma unroll
                    for (int nt = 0; nt < 2; nt++) {
                        float* d = acc[mt][np * 2 + nt];
                        mma_bf16(d, ah[mt], bh + nt * 2);
                        mma_bf16(d, al[mt], bh + nt * 2);
                        mma_bf16(d, ah[mt], bl + nt * 2);
                    }
                }
            }
        }
        __syncthreads();
    }

    // epilogue
    #pragma unroll
    for (int mt = 0; mt < 2; mt++) {
        int row0 = bm + warp_m * 32 + mt * 16 + (lane >> 2);
        #pragma unroll
        for (int np = 0; np < 4; np++) {
            #pragma unroll
            for (int nt = 0; nt < 2; nt++) {
                int col = bn + warp_n * 64 + np * 16 + nt * 8 + 2 * (lane & 3);
                float b0 = bias[col], b1 = bias[col + 1];
                const float* d = acc[mt][np * 2 + nt];
                float v0 = d[0] + b0, v1 = d[1] + b1;
                float v2 = d[2] + b0, v3 = d[3] + b1;
                if (relu) {
                    v0 = fmaxf(v0, 0.f); v1 = fmaxf(v1, 0.f);
                    v2 = fmaxf(v2, 0.f); v3 = fmaxf(v3, 0.f);
                }
                *reinterpret_cast<float2*>(C + (size_t)row0 * N + col)      = make_float2(v0, v1);
                *reinterpret_cast<float2*>(C + (size_t)(row0 + 8) * N + col) = make_float2(v2, v3);
            }
        }
    }
}

// ---------------- LayerNorm helper ------------------------------------------------
__device__ __forceinline__ float2 block_meanvar_256(float x, float* sbuf)
{
    float s = x, s2 = x * x;
    #pragma unroll
    for (int o = 16; o; o >>= 1) {
        s  += __shfl_xor_sync(0xffffffffu, s,  o);
        s2 += __shfl_xor_sync(0xffffffffu, s2, o);
    }
    int w = threadIdx.x >> 5;
    if ((threadIdx.x & 31) == 0) { sbuf[w] = s; sbuf[8 + w] = s2; }
    __syncthreads();
    float ts = 0.f, ts2 = 0.f;
    #pragma unroll
    for (int i = 0; i < 8; i++) { ts += sbuf[i]; ts2 += sbuf[8 + i]; }
    __syncthreads();
    float mean = ts * (1.f / 256.f);
    float var  = ts2 * (1.f / 256.f) - mean * mean;
    return make_float2(mean, rsqrtf(var + 1e-5f));
}

// ---------------- context encoder + node-count head --------------------------------
__global__ void k_context(
    const float* __restrict__ lat, const int* __restrict__ types,
    const float* __restrict__ w1, const float* __restrict__ b1,
    const float* __restrict__ g1, const float* __restrict__ be1,
    const float* __restrict__ w2, const float* __restrict__ b2,
    const float* __restrict__ g2, const float* __restrict__ be2,
    const float* __restrict__ ncw1, const float* __restrict__ ncb1,
    const float* __restrict__ ncw2, const float* __restrict__ ncb2,
    const float* __restrict__ temb, const float* __restrict__ pemb,
    float* __restrict__ out_nc)
{
    int b = blockIdx.x, t = threadIdx.x;
    __shared__ float sl[8];
    __shared__ float sh0[256];
    __shared__ float sred[16];
    __shared__ float snc[64];
    __shared__ int   sty[10];
    if (t < 8)  sl[t]  = lat[b * LD_ + t];
    if (t < 10) sty[t] = types[b * N_ + t];
    __syncthreads();

    float x = b1[t];
    #pragma unroll
    for (int k = 0; k < 8; k++) x += sl[k] * w1[k * H_ + t];
    float2 mv = block_meanvar_256(x, sred);
    float h0 = fmaxf((x - mv.x) * mv.y * g1[t] + be1[t], 0.f);
    sh0[t] = h0;
    __syncthreads();

    float y = b2[t];
    for (int k = 0; k < 256; k++) y += sh0[k] * w2[k * H_ + t];
    mv = block_meanvar_256(y, sred);
    float ctx = (y - mv.x) * mv.y * g2[t] + be2[t];

    g_ctx[b * H_ + t] = ctx;
    g_mem[(size_t)b * (M_ * H_) + t] = ctx;
    #pragma unroll
    for (int i = 0; i < N_; i++) {
        float pe = pemb[i * H_ + t];
        g_h  [((size_t)b * N_ + i) * H_ + t]     = ctx + pe;
        g_mem[((size_t)b * M_ + 1 + i) * H_ + t] = temb[sty[i] * H_ + t] + pe;
    }

    if (t < 64) snc[t] = fmaxf(sl[0] * ncw1[t] + sl[1] * ncw1[64 + t] + ncb1[t], 0.f);
    __syncthreads();
    if (t < 3) {
        float o = ncb2[t];
        #pragma unroll
        for (int k = 0; k < 64; k++) o += snc[k] * ncw2[k * 3 + t];
        out_nc[b * 3 + t] = o;
    }
}

// ---------------- attention --------------------------------------------------------
__global__ void k_attn()
{
    int b = blockIdx.x;
    int h = threadIdx.x >> 5, d = threadIdx.x & 31;
    const float* Qb = g_q + (size_t)b * N_ * H_;
    const float* Kb = g_k + (size_t)b * M_ * H_;
    const float* Vb = g_v + (size_t)b * M_ * H_;
    float*       Ob = g_o + (size_t)b * N_ * H_;
    const float scale = 0.17677669529663687f;

    #pragma unroll
    for (int i = 0; i < N_; i++) {
        float q = Qb[i * H_ + h * 32 + d];
        float sown = -1e30f;
        for (int m = 0; m <= i; m++) {
            float p = q * Kb[m * H_ + h * 32 + d];
            #pragma unroll
            for (int o = 16; o; o >>= 1) p += __shfl_xor_sync(0xffffffffu, p, o);
            if (d == m) sown = p * scale;
        }
        float mx = sown;
        #pragma unroll
        for (int o = 16; o; o >>= 1) mx = fmaxf(mx, __shfl_xor_sync(0xffffffffu, mx, o));
        float e = (d <= i) ? __expf(sown - mx) : 0.f;
        float den = e;
        #pragma unroll
        for (int o = 16; o; o >>= 1) den += __shfl_xor_sync(0xffffffffu, den, o);
        float oacc = 0.f;
        for (int m = 0; m <= i; m++) {
            float a = __shfl_sync(0xffffffffu, e, m);
            oacc += a * Vb[m * H_ + h * 32 + d];
        }
        Ob[i * H_ + h * 32 + d] = oacc / den;
    }
}

// ---------------- residual + LayerNorm ----------------------------------------------
__global__ void k_resln(const float* __restrict__ y,
                        const float* __restrict__ g, const float* __restrict__ b)
{
    int r = blockIdx.x, t = threadIdx.x;
    __shared__ float sred[16];
    size_t idx = (size_t)r * H_ + t;
    float x = g_h[idx] + y[idx];
    float2 mv = block_meanvar_256(x, sred);
    g_h[idx] = (x - mv.x) * mv.y * g[t] + b[t];
}

// ---------------- node-logits head ---------------------------------------------------
__global__ void k_head(const float* __restrict__ W, const float* __restrict__ bb,
                       float* __restrict__ out)
{
    int gid = blockIdx.x * blockDim.x + threadIdx.x;
    int row = gid >> 5, lane = gid & 31;
    if (row >= B_ * N_) return;
    const float* hr = g_h + (size_t)row * H_;
    float a0 = 0, a1 = 0, a2 = 0, a3 = 0, a4 = 0;
    #pragma unroll
    for (int qq = 0; qq < 8; qq++) {
        int k = lane + 32 * qq;
        float hv = hr[k];
        const float* w = W + k * 5;
        a0 += hv * w[0]; a1 += hv * w[1]; a2 += hv * w[2];
        a3 += hv * w[3]; a4 += hv * w[4];
    }
    #pragma unroll
    for (int o = 16; o; o >>= 1) {
        a0 += __shfl_xor_sync(0xffffffffu, a0, o);
        a1 += __shfl_xor_sync(0xffffffffu, a1, o);
        a2 += __shfl_xor_sync(0xffffffffu, a2, o);
        a3 += __shfl_xor_sync(0xffffffffu, a3, o);
        a4 += __shfl_xor_sync(0xffffffffu, a4, o);
    }
    if (lane < 5) {
        float v = (lane == 0) ? a0 : (lane == 1) ? a1 : (lane == 2) ? a2
                 : (lane == 3) ? a3 : a4;
        out[(size_t)row * 5 + lane] = v + bb[lane];
    }
}

// ---------------- edge decoder --------------------------------------------------------
__global__ void k_edge_uv(const float* __restrict__ temb, const float* __restrict__ pemb,
                          const float* __restrict__ w1)
{
    int tt = blockIdx.x / N_, p = blockIdx.x % N_;
    int j = threadIdx.x;
    __shared__ float ne[256];
    ne[j] = temb[tt * H_ + j] + pemb[p * H_ + j];
    __syncthreads();
    float au = 0.f, av = 0.f;
    for (int k = 0; k < 256; k++) {
        float n = ne[k];
        au += n * w1[k * H_ + j];
        av += n * w1[(256 + k) * H_ + j];
    }
    g_U [blockIdx.x * H_ + j] = au;
    g_Vt[blockIdx.x * H_ + j] = av;
}

__global__ void k_wlat(const float* __restrict__ lat, const float* __restrict__ w1,
                       const float* __restrict__ b1)
{
    int b = blockIdx.x, t = threadIdx.x;
    __shared__ float sl[8];
    if (t < 8) sl[t] = lat[b * LD_ + t];
    __syncthreads();
    float a = b1[t];
    #pragma unroll
    for (int k = 0; k < 8; k++) a += sl[k] * w1[(2 * H_ + k) * H_ + t];
    g_wlat[b * H_ + t] = a;
}

__global__ void k_edge(const int* __restrict__ types,
                       const float* __restrict__ W2, const float* __restrict__ b2,
                       float* __restrict__ out)
{
    int b = blockIdx.x, t = threadIdx.x;
    __shared__ float s_w[256];
    __shared__ float s_hid[256];
    __shared__ float s_W2t[8 * 256];
    __shared__ float s_b2[8];
    __shared__ int   s_ty[10];

    s_w[t] = g_wlat[b * H_ + t];
    #pragma unroll
    for (int c = 0; c < 8; c++) s_W2t[c * 256 + t] = W2[t * 8 + c];
    if (t < 10) s_ty[t] = types[b * N_ + t];
    if (t < 8)  s_b2[t] = b2[t];

    float* eb = out + (size_t)b * (N_ * N_ * 8);
    if (t < 80) { int i = t / 8, c = t % 8; eb[(i * N_ + i) * 8 + c] = 0.f; }
    __syncthreads();

    int lane = t & 31, w = t >> 5;
    for (int i = 1; i < N_; i++) {
        for (int j = 0; j < i; j++) {
            float hv = s_w[t] + g_U[(s_ty[i] * N_ + i) * H_ + t]
                              + g_Vt[(s_ty[j] * N_ + j) * H_ + t];
            s_hid[t] = fmaxf(hv, 0.f);
            __syncthreads();
            float acc = 0.f;
            #pragma unroll
            for (int qq = 0; qq < 8; qq++)
                acc += s_hid[lane + 32 * qq] * s_W2t[w * 256 + lane + 32 * qq];
            #pragma unroll
            for (int o = 16; o; o >>= 1) acc += __shfl_xor_sync(0xffffffffu, acc, o);
            if (lane == 0) {
                float v = acc + s_b2[w];
                eb[(i * N_ + j) * 8 + w] = v;
                eb[(j * N_ + i) * 8 + w] = v;
            }
            __syncthreads();
        }
    }
}

// ---------------- launcher --------------------------------------------------------
extern "C" void kernel_launch(void* const* d_in, const int* in_sizes, int n_in,
                              void* d_out, int out_size)
{
    (void)in_sizes; (void)n_in; (void)out_size;
    const float* latent  = (const float*)d_in[0];
    const int*   types   = (const int*)  d_in[1];
    const float* ce_w1   = (const float*)d_in[2];
    const float* ce_b1   = (const float*)d_in[3];
    const float* ce_g1   = (const float*)d_in[4];
    const float* ce_be1  = (const float*)d_in[5];
    const float* ce_w2   = (const float*)d_in[6];
    const float* ce_b2   = (const float*)d_in[7];
    const float* ce_g2   = (const float*)d_in[8];
    const float* ce_be2  = (const float*)d_in[9];
    const float* nc_w1   = (const float*)d_in[10];
    const float* nc_b1   = (const float*)d_in[11];
    const float* nc_w2   = (const float*)d_in[12];
    const float* nc_b2   = (const float*)d_in[13];
    const float* type_emb= (const float*)d_in[14];
    const float* pos_emb = (const float*)d_in[15];
    const float* qkvo_w  = (const float*)d_in[16];
    const float* qkvo_b  = (const float*)d_in[17];
    const float* ln_g    = (const float*)d_in[18];
    const float* ln_b    = (const float*)d_in[19];
    const float* ffn_w1  = (const float*)d_in[20];
    const float* ffn_b1  = (const float*)d_in[21];
    const float* ffn_w2  = (const float*)d_in[22];
    const float* ffn_b2  = (const float*)d_in[23];
    const float* out_w   = (const float*)d_in[24];
    const float* out_b   = (const float*)d_in[25];
    const float* edge_w1 = (const float*)d_in[26];
    const float* edge_b1 = (const float*)d_in[27];
    const float* edge_w2 = (const float*)d_in[28];
    const float* edge_b2 = (const float*)d_in[29];

    float* out      = (float*)d_out;
    float* out_node = out;
    float* out_nc   = out + (size_t)B_ * N_ * 5;
    float* out_edge = out + (size_t)B_ * N_ * 5 + B_ * 3;

    float *p_h, *p_mem, *p_q, *p_k, *p_v, *p_o, *p_y, *p_ffn;
    __nv_bfloat16 *p_wh, *p_wl;
    cudaGetSymbolAddress((void**)&p_h,   g_h);
    cudaGetSymbolAddress((void**)&p_mem, g_mem);
    cudaGetSymbolAddress((void**)&p_q,   g_q);
    cudaGetSymbolAddress((void**)&p_k,   g_k);
    cudaGetSymbolAddress((void**)&p_v,   g_v);
    cudaGetSymbolAddress((void**)&p_o,   g_o);
    cudaGetSymbolAddress((void**)&p_y,   g_y);
    cudaGetSymbolAddress((void**)&p_ffn, g_ffn);
    cudaGetSymbolAddress((void**)&p_wh,  g_wbh);
    cudaGetSymbolAddress((void**)&p_wl,  g_wbl);

    // weight prep (deterministic; every launch)
    k_prep_qkvo<<<L_ * 4 * 65536 / 256, 256>>>(qkvo_w);
    k_prep_ffn1<<<L_ * 262144 / 256, 256>>>(ffn_w1);
    k_prep_ffn2<<<L_ * 262144 / 256, 256>>>(ffn_w2);

    k_context<<<B_, 256>>>(latent, types, ce_w1, ce_b1, ce_g1, ce_be1,
                           ce_w2, ce_b2, ce_g2, ce_be2,
                           nc_w1, nc_b1, nc_w2, nc_b2,
                           type_emb, pos_emb, out_nc);
    k_edge_uv<<<NT_ * N_, 256>>>(type_emb, pos_emb, edge_w1);
    k_wlat<<<B_, 256>>>(latent, edge_w1, edge_b1);

    const int MQ = B_ * N_;   // 20480
    const int MK = B_ * M_;   // 22528

    for (int l = 0; l < L_; l++) {
        size_t wb = (size_t)l * 786432;
        const float* bq = qkvo_b + (size_t)(l * 4 + 0) * H_;
        const float* bk = qkvo_b + (size_t)(l * 4 + 1) * H_;
        const float* bv = qkvo_b + (size_t)(l * 4 + 2) * H_;
        const float* bo = qkvo_b + (size_t)(l * 4 + 3) * H_;

        k_gemm_mma<<<dim3(2, MQ / 128), 256>>>(
            p_h, p_wh + wb, p_wl + wb, bq, p_q, MQ, 256, 256, 0);
        k_gemm_mma<<<dim3(2, MK / 128), 256>>>(
            p_mem, p_wh + wb + 65536, p_wl + wb + 65536, bk, p_k, MK, 256, 256, 0);
        k_gemm_mma<<<dim3(2, MK / 128), 256>>>(
            p_mem, p_wh + wb + 131072, p_wl + wb + 131072, bv, p_v, MK, 256, 256, 0);
        k_attn<<<B_, 256>>>();
        k_gemm_mma<<<dim3(2, MQ / 128), 256>>>(
            p_o, p_wh + wb + 196608, p_wl + wb + 196608, bo, p_y, MQ, 256, 256, 0);
        k_resln<<<MQ, 256>>>(p_y, ln_g + (size_t)(l * 2 + 0) * H_, ln_b + (size_t)(l * 2 + 0) * H_);
        k_gemm_mma<<<dim3(8, MQ / 128), 256>>>(
            p_h, p_wh + wb + 262144, p_wl + wb + 262144,
            ffn_b1 + (size_t)l * FF_, p_ffn, MQ, 1024, 256, 1);
        k_gemm_mma<<<dim3(2, MQ / 128), 256>>>(
            p_ffn, p_wh + wb + 524288, p_wl + wb + 524288,
            ffn_b2 + (size_t)l * H_, p_y, MQ, 256, 1024, 0);
        k_resln<<<MQ, 256>>>(p_y, ln_g + (size_t)(l * 2 + 1) * H_, ln_b + (size_t)(l * 2 + 1) * H_);
    }

    k_head<<<(B_ * N_ * 32) / 256, 256>>>(out_w, out_b, out_node);
    k_edge<<<B_, 256>>>(types, edge_w2, edge_b2, out_edge);
}

// round 4
// speedup vs baseline: 2.0483x; 1.0289x over previous
#include <cuda_runtime.h>
#include <cuda_bf16.h>
#include <cstdint>

#define B_   2048
#define N_   10
#define H_   256
#define LD_  8
#define L_   4
#define FF_  1024
#define NT_  5

typedef __nv_bfloat16 bf16;

// ---------------- scratch -------------------------------------------------------
__device__ float g_h   [B_*N_*H_];
__device__ bf16  g_hh  [B_*N_*H_];
__device__ bf16  g_hl  [B_*N_*H_];
__device__ float g_q   [B_*N_*H_];
__device__ bf16  g_oh  [B_*N_*H_];
__device__ bf16  g_ol  [B_*N_*H_];
__device__ float g_y   [B_*N_*H_];
__device__ bf16  g_f1h [B_*N_*FF_];
__device__ bf16  g_f1l [B_*N_*FF_];
__device__ bf16  g_h0h [B_*H_];
__device__ bf16  g_h0l [B_*H_];
__device__ float g_ycf [B_*H_];
__device__ bf16  g_ctxh[B_*H_];
__device__ bf16  g_ctxl[B_*H_];
__device__ float g_kvctx[(size_t)B_*2048];     // [b][l*512 + (K:0..255 | V:256..511)]
__device__ float g_kvne [(size_t)128*2048];    // [combo(50,pad128)][same]
__device__ bf16  g_neAh[128*H_];
__device__ bf16  g_neAl[128*H_];
__device__ float g_U   [NT_*N_*H_];
__device__ float g_Vt  [NT_*N_*H_];
__device__ float g_wlat[B_*H_];
// weights (transposed [n][k], bf16 hi/lo)
__device__ bf16 g_wqh[L_*65536],  g_wql[L_*65536];
__device__ bf16 g_woh[L_*65536],  g_wol[L_*65536];
__device__ bf16 g_wkvh[L_*131072],g_wkvl[L_*131072];   // rows: l*512 + (k|v)
__device__ bf16 g_wf1h[(size_t)L_*262144], g_wf1l[(size_t)L_*262144];
__device__ bf16 g_wf2h[(size_t)L_*262144], g_wf2l[(size_t)L_*262144];
__device__ bf16 g_wce2h[65536], g_wce2l[65536];
__device__ float g_bkv[L_*512];

// ---------------- helpers --------------------------------------------------------
__device__ __forceinline__ uint32_t smem_u32(const void* p){
    uint32_t a; asm("{ .reg .u64 t; cvta.to.shared.u64 t, %1; cvt.u32.u64 %0, t; }"
                    : "=r"(a) : "l"(p)); return a;
}
__device__ __forceinline__ void cp16(uint32_t dst, const void* src){
    asm volatile("cp.async.ca.shared.global [%0], [%1], 16;"
                 :: "r"(dst), "l"(__cvta_generic_to_global(src)) : "memory");
}
__device__ __forceinline__ void ldm_x4(uint32_t* r, uint32_t addr){
    asm volatile("ldmatrix.sync.aligned.m8n8.x4.shared.b16 {%0,%1,%2,%3}, [%4];"
        : "=r"(r[0]),"=r"(r[1]),"=r"(r[2]),"=r"(r[3]) : "r"(addr));
}
__device__ __forceinline__ void mma_bf16(float* d, const uint32_t* a, const uint32_t* b){
    asm volatile("mma.sync.aligned.m16n8k16.row.col.f32.bf16.bf16.f32 "
        "{%0,%1,%2,%3}, {%4,%5,%6,%7}, {%8,%9}, {%0,%1,%2,%3};"
        : "+f"(d[0]),"+f"(d[1]),"+f"(d[2]),"+f"(d[3])
        : "r"(a[0]),"r"(a[1]),"r"(a[2]),"r"(a[3]), "r"(b[0]),"r"(b[1]));
}
__device__ __forceinline__ void split_store(bf16* ph, bf16* pl, size_t idx, float v){
    bf16 hi = __float2bfloat16(v);
    ph[idx] = hi; pl[idx] = __float2bfloat16(v - __bfloat162float(hi));
}

// ---------------- weight prep -----------------------------------------------------
__global__ void k_prep_qkvo(const float* __restrict__ w){   // [L,4,K,N]
    int idx = blockIdx.x * 256 + threadIdx.x;
    int mat = idx >> 16, k = (idx >> 8) & 255, n = idx & 255;
    int l = mat >> 2, m = mat & 3;
    float v = w[idx];
    bf16 h = __float2bfloat16(v);
    bf16 lo = __float2bfloat16(v - __bfloat162float(h));
    if (m == 0)      { size_t o = (size_t)l*65536 + n*256 + k; g_wqh[o]=h; g_wql[o]=lo; }
    else if (m == 1) { size_t o = (size_t)l*131072 + n*256 + k; g_wkvh[o]=h; g_wkvl[o]=lo; }
    else if (m == 2) { size_t o = (size_t)l*131072 + (256+n)*256 + k; g_wkvh[o]=h; g_wkvl[o]=lo; }
    else             { size_t o = (size_t)l*65536 + n*256 + k; g_woh[o]=h; g_wol[o]=lo; }
}
__global__ void k_prep_f1(const float* __restrict__ w){     // [L,256,1024]
    int idx = blockIdx.x * 256 + threadIdx.x;
    int l = idx >> 18, rem = idx & 262143, k = rem >> 10, n = rem & 1023;
    float v = w[idx];
    bf16 h = __float2bfloat16(v);
    size_t o = (size_t)l*262144 + (size_t)n*256 + k;
    g_wf1h[o] = h; g_wf1l[o] = __float2bfloat16(v - __bfloat162float(h));
}
__global__ void k_prep_f2(const float* __restrict__ w){     // [L,1024,256]
    int idx = blockIdx.x * 256 + threadIdx.x;
    int l = idx >> 18, rem = idx & 262143, k = rem >> 8, n = rem & 255;
    float v = w[idx];
    bf16 h = __float2bfloat16(v);
    size_t o = (size_t)l*262144 + (size_t)n*1024 + k;
    g_wf2h[o] = h; g_wf2l[o] = __float2bfloat16(v - __bfloat162float(h));
}
__global__ void k_prep_ce2(const float* __restrict__ w){    // [256,256]
    int idx = blockIdx.x * 256 + threadIdx.x;
    int k = idx >> 8, n = idx & 255;
    float v = w[idx];
    bf16 h = __float2bfloat16(v);
    g_wce2h[n*256 + k] = h;
    g_wce2l[n*256 + k] = __float2bfloat16(v - __bfloat162float(h));
}
__global__ void k_prep_bkv(const float* __restrict__ qkvo_b){
    int idx = blockIdx.x * 256 + threadIdx.x;   // < L*512
    int l = idx >> 9, c = idx & 511;
    g_bkv[idx] = (c < 256) ? qkvo_b[(l*4+1)*256 + c] : qkvo_b[(l*4+2)*256 + (c-256)];
}
__global__ void k_prep_ne(const float* __restrict__ temb, const float* __restrict__ pemb){
    int idx = blockIdx.x * 256 + threadIdx.x;   // < 128*256
    int row = idx >> 8, c = idx & 255;
    float v = 0.f;
    if (row < NT_*N_) { int t = row / N_, p = row % N_; v = temb[t*256+c] + pemb[p*256+c]; }
    split_store(g_neAh, g_neAl, idx, v);
}

// ---------------- cp.async double-buffered bf16-split mma GEMM --------------------
// C = A @ Bt^T + bias; A split [M,K], Bt split [N,K]. 128x128 tiles, chunks of 32.
#define ASTRIDE 40
#define STG_ARR 10240            // 128*40*2 bytes
#define STG_SZ  40960            // 4 arrays

__global__ __launch_bounds__(256)
void k_gemm(const bf16* __restrict__ Ah, const bf16* __restrict__ Al,
            const bf16* __restrict__ Bh, const bf16* __restrict__ Bl,
            const float* __restrict__ bias,
            float* __restrict__ Cf, bf16* __restrict__ Ch, bf16* __restrict__ Cl,
            int M, int N, int K, int relu)
{
    extern __shared__ char smem[];
    const uint32_t sb = smem_u32(smem);
    const int tid = threadIdx.x;
    const int wid = tid >> 5, lane = tid & 31;
    const int warp_m = wid & 3, warp_n = wid >> 2;
    const int bm = blockIdx.y * 128, bn = blockIdx.x * 128;

    float acc[2][8][4];
    #pragma unroll
    for (int i = 0; i < 2; i++)
        #pragma unroll
        for (int j = 0; j < 8; j++)
            #pragma unroll
            for (int q = 0; q < 4; q++) acc[i][j][q] = 0.f;

    const int sub  = lane >> 3;
    const int a_r  = (lane & 7) + ((sub & 1) << 3);
    const int a_kc = (sub >> 1) << 3;
    const int b_n  = (lane & 7) + ((sub >> 1) << 3);
    const int b_kc = (sub & 1) << 3;

    const int nc = K >> 5;

#define STAGE_LOAD(c, s) do {                                                  \
    const int k0_ = (c) * 32;                                                  \
    const uint32_t st_ = sb + (s) * STG_SZ;                                    \
    _Pragma("unroll")                                                          \
    for (int i_ = 0; i_ < 8; i_++) {                                           \
        int rem_ = ((i_ & 1) << 8) + tid;                                      \
        int row_ = rem_ >> 2, ch_ = rem_ & 3;                                  \
        const bf16* sp_;                                                       \
        if (i_ < 2)      sp_ = Ah + (size_t)(bm + row_) * K + k0_ + ch_ * 8;   \
        else if (i_ < 4) sp_ = Al + (size_t)(bm + row_) * K + k0_ + ch_ * 8;   \
        else if (i_ < 6) sp_ = Bh + (size_t)(bn + row_) * K + k0_ + ch_ * 8;   \
        else             sp_ = Bl + (size_t)(bn + row_) * K + k0_ + ch_ * 8;   \
        cp16(st_ + (i_ >> 1) * STG_ARR + (uint32_t)(row_ * ASTRIDE + ch_ * 8) * 2, sp_); \
    }                                                                          \
} while (0)

    STAGE_LOAD(0, 0);
    asm volatile("cp.async.commit_group;" ::: "memory");

    for (int c = 0; c < nc; c++) {
        const int s = c & 1;
        if (c + 1 < nc) {
            STAGE_LOAD(c + 1, s ^ 1);
            asm volatile("cp.async.commit_group;" ::: "memory");
            asm volatile("cp.async.wait_group 1;" ::: "memory");
        } else {
            asm volatile("cp.async.wait_group 0;" ::: "memory");
        }
        __syncthreads();

        const uint32_t ah_b = sb + s * STG_SZ;
        const uint32_t al_b = ah_b + STG_ARR;
        const uint32_t bh_b = ah_b + 2 * STG_ARR;
        const uint32_t bl_b = ah_b + 3 * STG_ARR;

        #pragma unroll
        for (int ks = 0; ks < 2; ks++) {
            uint32_t ah[2][4], al[2][4];
            #pragma unroll
            for (int mt = 0; mt < 2; mt++) {
                int rr = warp_m * 32 + mt * 16 + a_r;
                int kc = ks * 16 + a_kc;
                uint32_t off = (uint32_t)(rr * ASTRIDE + kc) * 2;
                ldm_x4(ah[mt], ah_b + off);
                ldm_x4(al[mt], al_b + off);
            }
            #pragma unroll
            for (int np = 0; np < 4; np++) {
                int nr = warp_n * 64 + np * 16 + b_n;
                int kc = ks * 16 + b_kc;
                uint32_t off = (uint32_t)(nr * ASTRIDE + kc) * 2;
                uint32_t bh[4], bl[4];
                ldm_x4(bh, bh_b + off);
                ldm_x4(bl, bl_b + off);
                #pragma unroll
                for (int mt = 0; mt < 2; mt++) {
                    #pragma unroll
                    for (int nt = 0; nt < 2; nt++) {
                        float* d = acc[mt][np * 2 + nt];
                        mma_bf16(d, ah[mt], bh + nt * 2);
                        mma_bf16(d, al[mt], bh + nt * 2);
                        mma_bf16(d, ah[mt], bl + nt * 2);
                    }
                }
            }
        }
        __syncthreads();
    }

    // epilogue
    #pragma unroll
    for (int mt = 0; mt < 2; mt++) {
        int row0 = bm + warp_m * 32 + mt * 16 + (lane >> 2);
        #pragma unroll
        for (int np = 0; np < 4; np++) {
            #pragma unroll
            for (int nt = 0; nt < 2; nt++) {
                int col = bn + warp_n * 64 + np * 16 + nt * 8 + 2 * (lane & 3);
                float b0 = bias[col], b1 = bias[col + 1];
                const float* d = acc[mt][np * 2 + nt];
                float v0 = d[0] + b0, v1 = d[1] + b1;
                float v2 = d[2] + b0, v3 = d[3] + b1;
                if (relu) {
                    v0 = fmaxf(v0, 0.f); v1 = fmaxf(v1, 0.f);
                    v2 = fmaxf(v2, 0.f); v3 = fmaxf(v3, 0.f);
                }
                size_t i0 = (size_t)row0 * N + col;
                size_t i1 = (size_t)(row0 + 8) * N + col;
                if (Cf) {
                    *reinterpret_cast<float2*>(Cf + i0) = make_float2(v0, v1);
                    *reinterpret_cast<float2*>(Cf + i1) = make_float2(v2, v3);
                }
                if (Ch) {
                    split_store(Ch, Cl, i0,     v0);
                    split_store(Ch, Cl, i0 + 1, v1);
                    split_store(Ch, Cl, i1,     v2);
                    split_store(Ch, Cl, i1 + 1, v3);
                }
            }
        }
    }
}

// ---------------- LayerNorm helper ------------------------------------------------
__device__ __forceinline__ float2 block_meanvar_256(float x, float* sbuf)
{
    float s = x, s2 = x * x;
    #pragma unroll
    for (int o = 16; o; o >>= 1) {
        s  += __shfl_xor_sync(0xffffffffu, s,  o);
        s2 += __shfl_xor_sync(0xffffffffu, s2, o);
    }
    int w = threadIdx.x >> 5;
    if ((threadIdx.x & 31) == 0) { sbuf[w] = s; sbuf[8 + w] = s2; }
    __syncthreads();
    float ts = 0.f, ts2 = 0.f;
    #pragma unroll
    for (int i = 0; i < 8; i++) { ts += sbuf[i]; ts2 += sbuf[8 + i]; }
    __syncthreads();
    float mean = ts * (1.f / 256.f);
    float var  = ts2 * (1.f / 256.f) - mean * mean;
    return make_float2(mean, rsqrtf(var + 1e-5f));
}

// ---------------- context stage 1: ce1 + LN + relu + node-count -------------------
__global__ void k_ctx1(
    const float* __restrict__ lat,
    const float* __restrict__ w1, const float* __restrict__ b1,
    const float* __restrict__ g1, const float* __restrict__ be1,
    const float* __restrict__ ncw1, const float* __restrict__ ncb1,
    const float* __restrict__ ncw2, const float* __restrict__ ncb2,
    float* __restrict__ out_nc)
{
    int b = blockIdx.x, t = threadIdx.x;
    __shared__ float sl[8];
    __shared__ float sred[16];
    __shared__ float snc[64];
    if (t < 8) sl[t] = lat[b * LD_ + t];
    __syncthreads();

    float x = b1[t];
    #pragma unroll
    for (int k = 0; k < 8; k++) x += sl[k] * w1[k * H_ + t];
    float2 mv = block_meanvar_256(x, sred);
    float h0 = fmaxf((x - mv.x) * mv.y * g1[t] + be1[t], 0.f);
    split_store(g_h0h, g_h0l, (size_t)b * H_ + t, h0);

    if (t < 64) snc[t] = fmaxf(sl[0] * ncw1[t] + sl[1] * ncw1[64 + t] + ncb1[t], 0.f);
    __syncthreads();
    if (t < 3) {
        float o = ncb2[t];
        #pragma unroll
        for (int k = 0; k < 64; k++) o += snc[k] * ncw2[k * 3 + t];
        out_nc[b * 3 + t] = o;
    }
}

// ---------------- context stage 2: LN(ce2 out) -> ctx, h --------------------------
__global__ void k_ctx2(const float* __restrict__ pemb,
                       const float* __restrict__ g2, const float* __restrict__ be2)
{
    int b = blockIdx.x, t = threadIdx.x;
    __shared__ float sred[16];
    float y = g_ycf[(size_t)b * H_ + t];
    float2 mv = block_meanvar_256(y, sred);
    float ctx = (y - mv.x) * mv.y * g2[t] + be2[t];
    split_store(g_ctxh, g_ctxl, (size_t)b * H_ + t, ctx);
    #pragma unroll
    for (int i = 0; i < N_; i++) {
        float hv = ctx + pemb[i * H_ + t];
        size_t idx = ((size_t)b * N_ + i) * H_ + t;
        g_h[idx] = hv;
        split_store(g_hh, g_hl, idx, hv);
    }
}

// ---------------- attention --------------------------------------------------------
__global__ void k_attn(int l, const int* __restrict__ types)
{
    int b = blockIdx.x;
    int h = threadIdx.x >> 5, d = threadIdx.x & 31;
    __shared__ int sty[10];
    if (threadIdx.x < 10) sty[threadIdx.x] = types[b * N_ + threadIdx.x];
    __syncthreads();
    int col = h * 32 + d;
    float Kr[11], Vr[11];
    size_t cb = (size_t)b * 2048 + l * 512 + col;
    Kr[0] = g_kvctx[cb]; Vr[0] = g_kvctx[cb + 256];
    #pragma unroll
    for (int m = 1; m <= 10; m++) {
        int combo = sty[m - 1] * N_ + (m - 1);
        size_t nb = (size_t)combo * 2048 + l * 512 + col;
        Kr[m] = g_kvne[nb]; Vr[m] = g_kvne[nb + 256];
    }
    const float scale = 0.17677669529663687f;
    for (int i = 0; i < N_; i++) {
        float q = g_q[((size_t)b * N_ + i) * H_ + col];
        float sown = -1e30f;
        for (int m = 0; m <= i; m++) {
            float p = q * Kr[m];
            #pragma unroll
            for (int o = 16; o; o >>= 1) p += __shfl_xor_sync(0xffffffffu, p, o);
            if (d == m) sown = p * scale;
        }
        float mx = sown;
        #pragma unroll
        for (int o = 16; o; o >>= 1) mx = fmaxf(mx, __shfl_xor_sync(0xffffffffu, mx, o));
        float e = (d <= i) ? __expf(sown - mx) : 0.f;
        float den = e;
        #pragma unroll
        for (int o = 16; o; o >>= 1) den += __shfl_xor_sync(0xffffffffu, den, o);
        float oacc = 0.f;
        for (int m = 0; m <= i; m++) {
            float a = __shfl_sync(0xffffffffu, e, m);
            oacc += a * Vr[m];
        }
        float v = oacc / den;
        split_store(g_oh, g_ol, ((size_t)b * N_ + i) * H_ + col, v);
    }
}

// ---------------- residual + LayerNorm ---------------------------------------------
__global__ void k_resln(const float* __restrict__ y,
                        const float* __restrict__ g, const float* __restrict__ b)
{
    int r = blockIdx.x, t = threadIdx.x;
    __shared__ float sred[16];
    size_t idx = (size_t)r * H_ + t;
    float x = g_h[idx] + y[idx];
    float2 mv = block_meanvar_256(x, sred);
    float v = (x - mv.x) * mv.y * g[t] + b[t];
    g_h[idx] = v;
    split_store(g_hh, g_hl, idx, v);
}

// ---------------- node-logits head ---------------------------------------------------
__global__ void k_head(const float* __restrict__ W, const float* __restrict__ bb,
                       float* __restrict__ out)
{
    int gid = blockIdx.x * blockDim.x + threadIdx.x;
    int row = gid >> 5, lane = gid & 31;
    if (row >= B_ * N_) return;
    const float* hr = g_h + (size_t)row * H_;
    float a0 = 0, a1 = 0, a2 = 0, a3 = 0, a4 = 0;
    #pragma unroll
    for (int qq = 0; qq < 8; qq++) {
        int k = lane + 32 * qq;
        float hv = hr[k];
        const float* w = W + k * 5;
        a0 += hv * w[0]; a1 += hv * w[1]; a2 += hv * w[2];
        a3 += hv * w[3]; a4 += hv * w[4];
    }
    #pragma unroll
    for (int o = 16; o; o >>= 1) {
        a0 += __shfl_xor_sync(0xffffffffu, a0, o);
        a1 += __shfl_xor_sync(0xffffffffu, a1, o);
        a2 += __shfl_xor_sync(0xffffffffu, a2, o);
        a3 += __shfl_xor_sync(0xffffffffu, a3, o);
        a4 += __shfl_xor_sync(0xffffffffu, a4, o);
    }
    if (lane < 5) {
        float v = (lane == 0) ? a0 : (lane == 1) ? a1 : (lane == 2) ? a2
                 : (lane == 3) ? a3 : a4;
        out[(size_t)row * 5 + lane] = v + bb[lane];
    }
}

// ---------------- edge decoder --------------------------------------------------------
__global__ void k_edge_uv(const float* __restrict__ temb, const float* __restrict__ pemb,
                          const float* __restrict__ w1)
{
    int tt = blockIdx.x / N_, p = blockIdx.x % N_;
    int j = threadIdx.x;
    __shared__ float ne[256];
    ne[j] = temb[tt * H_ + j] + pemb[p * H_ + j];
    __syncthreads();
    float au = 0.f, av = 0.f;
    for (int k = 0; k < 256; k++) {
        float n = ne[k];
        au += n * w1[k * H_ + j];
        av += n * w1[(256 + k) * H_ + j];
    }
    g_U [blockIdx.x * H_ + j] = au;
    g_Vt[blockIdx.x * H_ + j] = av;
}

__global__ void k_wlat(const float* __restrict__ lat, const float* __restrict__ w1,
                       const float* __restrict__ b1)
{
    int b = blockIdx.x, t = threadIdx.x;
    __shared__ float sl[8];
    if (t < 8) sl[t] = lat[b * LD_ + t];
    __syncthreads();
    float a = b1[t];
    #pragma unroll
    for (int k = 0; k < 8; k++) a += sl[k] * w1[(2 * H_ + k) * H_ + t];
    g_wlat[b * H_ + t] = a;
}

__global__ void k_edge(const int* __restrict__ types,
                       const float* __restrict__ W2, const float* __restrict__ b2,
                       float* __restrict__ out)
{
    int b = blockIdx.x, t = threadIdx.x;
    __shared__ float s_w[256];
    __shared__ float s_hid[256];
    __shared__ float s_W2t[8 * 256];
    __shared__ float s_b2[8];
    __shared__ int   s_ty[10];

    s_w[t] = g_wlat[b * H_ + t];
    #pragma unroll
    for (int c = 0; c < 8; c++) s_W2t[c * 256 + t] = W2[t * 8 + c];
    if (t < 10) s_ty[t] = types[b * N_ + t];
    if (t < 8)  s_b2[t] = b2[t];

    float* eb = out + (size_t)b * (N_ * N_ * 8);
    if (t < 80) { int i = t / 8, c = t % 8; eb[(i * N_ + i) * 8 + c] = 0.f; }
    __syncthreads();

    int lane = t & 31, w = t >> 5;
    for (int i = 1; i < N_; i++) {
        for (int j = 0; j < i; j++) {
            float hv = s_w[t] + g_U[(s_ty[i] * N_ + i) * H_ + t]
                              + g_Vt[(s_ty[j] * N_ + j) * H_ + t];
            s_hid[t] = fmaxf(hv, 0.f);
            __syncthreads();
            float acc = 0.f;
            #pragma unroll
            for (int qq = 0; qq < 8; qq++)
                acc += s_hid[lane + 32 * qq] * s_W2t[w * 256 + lane + 32 * qq];
            #pragma unroll
            for (int o = 16; o; o >>= 1) acc += __shfl_xor_sync(0xffffffffu, acc, o);
            if (lane == 0) {
                float v = acc + s_b2[w];
                eb[(i * N_ + j) * 8 + w] = v;
                eb[(j * N_ + i) * 8 + w] = v;
            }
            __syncthreads();
        }
    }
}

// ---------------- launcher --------------------------------------------------------
extern "C" void kernel_launch(void* const* d_in, const int* in_sizes, int n_in,
                              void* d_out, int out_size)
{
    (void)in_sizes; (void)n_in; (void)out_size;
    const float* latent  = (const float*)d_in[0];
    const int*   types   = (const int*)  d_in[1];
    const float* ce_w1   = (const float*)d_in[2];
    const float* ce_b1   = (const float*)d_in[3];
    const float* ce_g1   = (const float*)d_in[4];
    const float* ce_be1  = (const float*)d_in[5];
    const float* ce_w2   = (const float*)d_in[6];
    const float* ce_b2   = (const float*)d_in[7];
    const float* ce_g2   = (const float*)d_in[8];
    const float* ce_be2  = (const float*)d_in[9];
    const float* nc_w1   = (const float*)d_in[10];
    const float* nc_b1   = (const float*)d_in[11];
    const float* nc_w2   = (const float*)d_in[12];
    const float* nc_b2   = (const float*)d_in[13];
    const float* type_emb= (const float*)d_in[14];
    const float* pos_emb = (const float*)d_in[15];
    const float* qkvo_w  = (const float*)d_in[16];
    const float* qkvo_b  = (const float*)d_in[17];
    const float* ln_g    = (const float*)d_in[18];
    const float* ln_b    = (const float*)d_in[19];
    const float* ffn_w1  = (const float*)d_in[20];
    const float* ffn_b1  = (const float*)d_in[21];
    const float* ffn_w2  = (const float*)d_in[22];
    const float* ffn_b2  = (const float*)d_in[23];
    const float* out_w   = (const float*)d_in[24];
    const float* out_b   = (const float*)d_in[25];
    const float* edge_w1 = (const float*)d_in[26];
    const float* edge_b1 = (const float*)d_in[27];
    const float* edge_w2 = (const float*)d_in[28];
    const float* edge_b2 = (const float*)d_in[29];

    float* out      = (float*)d_out;
    float* out_node = out;
    float* out_nc   = out + (size_t)B_ * N_ * 5;
    float* out_edge = out + (size_t)B_ * N_ * 5 + B_ * 3;

    // device pointers to globals
    float *p_h, *p_q, *p_y, *p_ycf, *p_kvctx, *p_kvne;
    bf16 *p_hh, *p_hl, *p_oh, *p_ol, *p_f1h, *p_f1l, *p_h0h, *p_h0l,
         *p_ctxh, *p_ctxl, *p_neAh, *p_neAl;
    bf16 *p_wqh, *p_wql, *p_woh, *p_wol, *p_wkvh, *p_wkvl,
         *p_wf1h, *p_wf1l, *p_wf2h, *p_wf2l, *p_wce2h, *p_wce2l;
    float *p_bkv;
    cudaGetSymbolAddress((void**)&p_h,    g_h);
    cudaGetSymbolAddress((void**)&p_q,    g_q);
    cudaGetSymbolAddress((void**)&p_y,    g_y);
    cudaGetSymbolAddress((void**)&p_ycf,  g_ycf);
    cudaGetSymbolAddress((void**)&p_kvctx,g_kvctx);
    cudaGetSymbolAddress((void**)&p_kvne, g_kvne);
    cudaGetSymbolAddress((void**)&p_hh,   g_hh);
    cudaGetSymbolAddress((void**)&p_hl,   g_hl);
    cudaGetSymbolAddress((void**)&p_oh,   g_oh);
    cudaGetSymbolAddress((void**)&p_ol,   g_ol);
    cudaGetSymbolAddress((void**)&p_f1h,  g_f1h);
    cudaGetSymbolAddress((void**)&p_f1l,  g_f1l);
    cudaGetSymbolAddress((void**)&p_h0h,  g_h0h);
    cudaGetSymbolAddress((void**)&p_h0l,  g_h0l);
    cudaGetSymbolAddress((void**)&p_ctxh, g_ctxh);
    cudaGetSymbolAddress((void**)&p_ctxl, g_ctxl);
    cudaGetSymbolAddress((void**)&p_neAh, g_neAh);
    cudaGetSymbolAddress((void**)&p_neAl, g_neAl);
    cudaGetSymbolAddress((void**)&p_wqh,  g_wqh);
    cudaGetSymbolAddress((void**)&p_wql,  g_wql);
    cudaGetSymbolAddress((void**)&p_woh,  g_woh);
    cudaGetSymbolAddress((void**)&p_wol,  g_wol);
    cudaGetSymbolAddress((void**)&p_wkvh, g_wkvh);
    cudaGetSymbolAddress((void**)&p_wkvl, g_wkvl);
    cudaGetSymbolAddress((void**)&p_wf1h, g_wf1h);
    cudaGetSymbolAddress((void**)&p_wf1l, g_wf1l);
    cudaGetSymbolAddress((void**)&p_wf2h, g_wf2h);
    cudaGetSymbolAddress((void**)&p_wf2l, g_wf2l);
    cudaGetSymbolAddress((void**)&p_wce2h,g_wce2h);
    cudaGetSymbolAddress((void**)&p_wce2l,g_wce2l);
    cudaGetSymbolAddress((void**)&p_bkv,  g_bkv);

    cudaFuncSetAttribute(k_gemm, cudaFuncAttributeMaxDynamicSharedMemorySize, 2 * STG_SZ);

    // weight prep
    k_prep_qkvo<<<L_ * 4 * 65536 / 256, 256>>>(qkvo_w);
    k_prep_f1<<<L_ * 262144 / 256, 256>>>(ffn_w1);
    k_prep_f2<<<L_ * 262144 / 256, 256>>>(ffn_w2);
    k_prep_ce2<<<65536 / 256, 256>>>(ce_w2);
    k_prep_bkv<<<L_ * 512 / 256, 256>>>(qkvo_b);
    k_prep_ne<<<128 * 256 / 256, 256>>>(type_emb, pos_emb);

    // context path
    k_ctx1<<<B_, 256>>>(latent, ce_w1, ce_b1, ce_g1, ce_be1,
                        nc_w1, nc_b1, nc_w2, nc_b2, out_nc);
    k_gemm<<<dim3(2, 16), 256, 2*STG_SZ>>>(p_h0h, p_h0l, p_wce2h, p_wce2l,
                                           ce_b2, p_ycf, nullptr, nullptr,
                                           2048, 256, 256, 0);
    k_ctx2<<<B_, 256>>>(pos_emb, ce_g2, ce_be2);

    // edge precompute (independent)
    k_edge_uv<<<NT_ * N_, 256>>>(type_emb, pos_emb, edge_w1);
    k_wlat<<<B_, 256>>>(latent, edge_w1, edge_b1);

    // K/V for all layers (ctx rows + ne table rows)
    k_gemm<<<dim3(16, 16), 256, 2*STG_SZ>>>(p_ctxh, p_ctxl, p_wkvh, p_wkvl,
                                            p_bkv, p_kvctx, nullptr, nullptr,
                                            2048, 2048, 256, 0);
    k_gemm<<<dim3(16, 1), 256, 2*STG_SZ>>>(p_neAh, p_neAl, p_wkvh, p_wkvl,
                                           p_bkv, p_kvne, nullptr, nullptr,
                                           128, 2048, 256, 0);

    const int MQ = B_ * N_;   // 20480
    for (int l = 0; l < L_; l++) {
        k_gemm<<<dim3(2, MQ/128), 256, 2*STG_SZ>>>(
            p_hh, p_hl, p_wqh + (size_t)l*65536, p_wql + (size_t)l*65536,
            qkvo_b + (size_t)(l*4)*H_, p_q, nullptr, nullptr, MQ, 256, 256, 0);
        k_attn<<<B_, 256>>>(l, types);
        k_gemm<<<dim3(2, MQ/128), 256, 2*STG_SZ>>>(
            p_oh, p_ol, p_woh + (size_t)l*65536, p_wol + (size_t)l*65536,
            qkvo_b + (size_t)(l*4+3)*H_, p_y, nullptr, nullptr, MQ, 256, 256, 0);
        k_resln<<<MQ, 256>>>(p_y, ln_g + (size_t)(l*2)*H_, ln_b + (size_t)(l*2)*H_);
        k_gemm<<<dim3(8, MQ/128), 256, 2*STG_SZ>>>(
            p_hh, p_hl, p_wf1h + (size_t)l*262144, p_wf1l + (size_t)l*262144,
            ffn_b1 + (size_t)l*FF_, nullptr, p_f1h, p_f1l, MQ, 1024, 256, 1);
        k_gemm<<<dim3(2, MQ/128), 256, 2*STG_SZ>>>(
            p_f1h, p_f1l, p_wf2h + (size_t)l*262144, p_wf2l + (size_t)l*262144,
            ffn_b2 + (size_t)l*H_, p_y, nullptr, nullptr, MQ, 256, 1024, 0);
        k_resln<<<MQ, 256>>>(p_y, ln_g + (size_t)(l*2+1)*H_, ln_b + (size_t)(l*2+1)*H_);
    }

    k_head<<<(B_ * N_ * 32) / 256, 256>>>(out_w, out_b, out_node);
    k_edge<<<B_, 256>>>(types, edge_w2, edge_b2, out_edge);
}